// round 16
// baseline (speedup 1.0000x reference)
#include <cuda_runtime.h>
#include <cstdint>

// MixtureLowRankRNN — GB300 sm_103a. Single fused kernel.
// Subspace identity: h_t ∈ colspan([m|I]) (h0=0) ⇒ outputs are basis coords:
//   y[:,t,0:4]  = a_s*S_{t+1},  S <- 0.9 S + u_t,  u_t = n^T tanh(h_t)
//   y[:,t,4:20] = 0.1*X_{t+1},  X <- 0.9 X + x_t
// Round 11: cross-warp combine via smem atomicAdd running sums (lane0 of each
// warp adds its redux partial; readers diff against a register copy of the
// previous total — int wraparound keeps differences exact; double-buffered by
// t&1 for race freedom). Replaces 8xLDS.128+12 IADD with 1xLDS.128+4 ISUB.

#define RANKN 4
#define INPN  16
#define TLEN  1024
#define BATCH 32
#define NTHR  256

#define S_Q   2097152.0f     // 2^21 fixed-point scale

typedef unsigned long long u64;

#define SMEM_X_BYTES  (TLEN * INPN * 8)          // duplicated pairs: 128 KB
#define SMEM_TOTAL    SMEM_X_BYTES

__device__ __forceinline__ u64 pack2(float x, float y) {
    u64 r; asm("mov.b64 %0, {%1, %2};" : "=l"(r) : "f"(x), "f"(y)); return r;
}
__device__ __forceinline__ void unpack2(u64 v, float& x, float& y) {
    asm("mov.b64 {%0, %1}, %2;" : "=f"(x), "=f"(y) : "l"(v));
}
__device__ __forceinline__ u64 fma2(u64 a, u64 b, u64 c) {
    u64 d; asm("fma.rn.f32x2 %0, %1, %2, %3;" : "=l"(d) : "l"(a), "l"(b), "l"(c)); return d;
}
__device__ __forceinline__ u64 mul2(u64 a, u64 b) {
    u64 d; asm("mul.rn.f32x2 %0, %1, %2;" : "=l"(d) : "l"(a), "l"(b)); return d;
}
__device__ __forceinline__ u64 add2(u64 a, u64 b) {
    u64 d; asm("add.rn.f32x2 %0, %1, %2;" : "=l"(d) : "l"(a), "l"(b)); return d;
}
__device__ __forceinline__ float tanha(float x) {
    float r; asm("tanh.approx.f32 %0, %1;" : "=f"(r) : "f"(x)); return r;
}
__device__ __forceinline__ int redux_s32(int v) {
    int r; asm("redux.sync.add.s32 %0, %1, 0xffffffff;" : "=r"(r) : "r"(v)); return r;
}

__global__ __launch_bounds__(NTHR, 1)
void rnn_fused(const float* __restrict__ x,   // [B, T, 16]
               const float* __restrict__ m,   // [H, 4]
               const float* __restrict__ n,   // [H, 4]
               const float* __restrict__ I,   // [H, 16]
               float* __restrict__ out)       // [B, T, 20]
{
    extern __shared__ char smem[];
    u64* s_xd = (u64*)smem;                    // [TLEN*16] duplicated x pairs

    __shared__ uint4 s_acc[2];                 // running-sum accumulators

    const int b    = blockIdx.x;
    const int tid  = threadIdx.x;
    const int wid  = tid >> 5;
    const int lane = tid & 31;

    const float a_s  = 0.1f * (500.0f / 1024.0f);
    const float invS = 1.0f / S_Q;

    // ---- stage the whole batch's x into smem, duplicated as f32x2 pairs ----
    const float* xb = x + (size_t)b * TLEN * INPN;
    {
        const float4* xr4 = (const float4*)xb;
        for (int idx = tid; idx < TLEN * INPN / 4; idx += NTHR) {
            float4 f = xr4[idx];
            s_xd[idx * 4 + 0] = pack2(f.x, f.x);
            s_xd[idx * 4 + 1] = pack2(f.y, f.y);
            s_xd[idx * 4 + 2] = pack2(f.z, f.z);
            s_xd[idx * 4 + 3] = pack2(f.w, f.w);
        }
    }
    if (tid < 2) s_acc[tid] = make_uint4(0u, 0u, 0u, 0u);

    // ---- weights in registers (pairs: A=(tid,tid+256), B=(tid+512,tid+768)) ----
    const int eA0 = tid,       eA1 = tid + 256;
    const int eB0 = tid + 512, eB1 = tid + 768;

    u64 naA[RANKN], naB[RANKN], mcA[RANKN], mcB[RANKN], Ia[INPN], Ib[INPN];
#pragma unroll
    for (int r = 0; r < RANKN; r++) {
        naA[r] = pack2(S_Q * n[eA0 * RANKN + r], S_Q * n[eA1 * RANKN + r]);
        naB[r] = pack2(S_Q * n[eB0 * RANKN + r], S_Q * n[eB1 * RANKN + r]);
        mcA[r] = pack2(a_s * invS * m[eA0 * RANKN + r], a_s * invS * m[eA1 * RANKN + r]);
        mcB[r] = pack2(a_s * invS * m[eB0 * RANKN + r], a_s * invS * m[eB1 * RANKN + r]);
    }
#pragma unroll
    for (int j = 0; j < INPN; j++) {
        Ia[j] = pack2(0.1f * I[eA0 * INPN + j], 0.1f * I[eA1 * INPN + j]);
        Ib[j] = pack2(0.1f * I[eB0 * INPN + j], 0.1f * I[eB1 * INPN + j]);
    }

    const u64 c9  = pack2(0.9f, 0.9f);
    const u64 asq = pack2(a_s * invS, a_s * invS);

    float* outb = out + (size_t)b * TLEN * 20;

    u64 hA = 0ull, hB = 0ull;
    u64 S01 = 0ull, S23 = 0ull;      // warp0 lane0, scaled domain
    float X = 0.f;                   // warp1 lanes 0..15

    unsigned pv0[4] = {0u, 0u, 0u, 0u};   // prev totals, buffer 0
    unsigned pv1[4] = {0u, 0u, 0u, 0u};   // prev totals, buffer 1

    __syncthreads();   // x staging + acc init complete

    auto step = [&](int t, int p, unsigned* pv) {
        // ---- critical path: tanh(h), scaled low-rank dot, int redux ----
        float a0, a1, b0v, b1v;
        unpack2(hA, a0, a1); unpack2(hB, b0v, b1v);
        u64 thA = pack2(tanha(a0), tanha(a1));
        u64 thB = pack2(tanha(b0v), tanha(b1v));

        int pi[4];
#pragma unroll
        for (int r = 0; r < RANKN; r++) {
            float lo, hi; unpack2(fma2(naB[r], thB, mul2(naA[r], thA)), lo, hi);
            pi[r] = redux_s32(__float2int_rn(lo + hi));
        }
        // one warp representative adds into the running total (wraparound-safe)
        if (lane == 0) {
            unsigned* acc = (unsigned*)&s_acc[p];
            atomicAdd(&acc[0], (unsigned)pi[0]);
            atomicAdd(&acc[1], (unsigned)pi[1]);
            atomicAdd(&acc[2], (unsigned)pi[2]);
            atomicAdd(&acc[3], (unsigned)pi[3]);
        }

        // ---- u-independent update from smem x: 8 LDS.128 + 4 parallel chains ----
        const ulonglong2* xp = (const ulonglong2*)(s_xd + (size_t)t * INPN);
        ulonglong2 xq0 = xp[0], xq1 = xp[1], xq2 = xp[2], xq3 = xp[3];
        u64 aA0 = fma2(c9, hA, mul2(Ia[0], xq0.x));
        u64 aB0 = fma2(c9, hB, mul2(Ib[0], xq0.x));
        u64 aA1 = fma2(Ia[2], xq1.x, mul2(Ia[1], xq0.y));
        u64 aB1 = fma2(Ib[2], xq1.x, mul2(Ib[1], xq0.y));
        u64 aA2 = fma2(Ia[4], xq2.x, mul2(Ia[3], xq1.y));
        u64 aB2 = fma2(Ib[4], xq2.x, mul2(Ib[3], xq1.y));
        u64 aA3 = fma2(Ia[6], xq3.x, mul2(Ia[5], xq2.y));
        u64 aB3 = fma2(Ib[6], xq3.x, mul2(Ib[5], xq2.y));
        ulonglong2 xq4 = xp[4], xq5 = xp[5], xq6 = xp[6], xq7 = xp[7];
        aA0 = fma2(Ia[7],  xq3.y, aA0);  aB0 = fma2(Ib[7],  xq3.y, aB0);
        aA1 = fma2(Ia[8],  xq4.x, aA1);  aB1 = fma2(Ib[8],  xq4.x, aB1);
        aA2 = fma2(Ia[9],  xq4.y, aA2);  aB2 = fma2(Ib[9],  xq4.y, aB2);
        aA3 = fma2(Ia[10], xq5.x, aA3);  aB3 = fma2(Ib[10], xq5.x, aB3);
        aA0 = fma2(Ia[11], xq5.y, aA0);  aB0 = fma2(Ib[11], xq5.y, aB0);
        aA1 = fma2(Ia[12], xq6.x, aA1);  aB1 = fma2(Ib[12], xq6.x, aB1);
        aA2 = fma2(Ia[13], xq6.y, aA2);  aB2 = fma2(Ib[13], xq6.y, aB2);
        aA3 = fma2(Ia[14], xq7.x, aA3);  aB3 = fma2(Ib[14], xq7.x, aB3);
        aA0 = fma2(Ia[15], xq7.y, aA0);  aB0 = fma2(Ib[15], xq7.y, aB0);
        u64 accA = add2(add2(aA0, aA1), add2(aA2, aA3));
        u64 accB = add2(add2(aB0, aB1), add2(aB2, aB3));

        // ---- input-coordinate output (warp1, off critical path) ----
        if (wid == 1 && lane < INPN) {
            float xv = *(const float*)(s_xd + (size_t)t * INPN + lane);  // low half
            X = fmaf(0.9f, X, xv);
            outb[(size_t)t * 20 + 4 + lane] = 0.1f * X;
        }

        __syncthreads();   // the only barrier per step

        // ---- combine: ONE LDS.128 + diff against previous total ----
        uint4 cur = s_acc[p];
        int U0 = (int)(cur.x - pv[0]);
        int U1 = (int)(cur.y - pv[1]);
        int U2 = (int)(cur.z - pv[2]);
        int U3 = (int)(cur.w - pv[3]);
        pv[0] = cur.x; pv[1] = cur.y; pv[2] = cur.z; pv[3] = cur.w;

        float uf0 = (float)U0, uf1 = (float)U1;   // S_Q * u_r
        float uf2 = (float)U2, uf3 = (float)U3;
        u64 U0d = pack2(uf0, uf0), U1d = pack2(uf1, uf1);
        u64 U2d = pack2(uf2, uf2), U3d = pack2(uf3, uf3);

        // h_{t+1} = acc + sum_r (a_s m_r / S_Q) * (S_Q u_r)
        u64 cA0 = fma2(mcA[1], U1d, mul2(mcA[0], U0d));
        u64 cB0 = fma2(mcB[1], U1d, mul2(mcB[0], U0d));
        u64 cA1 = fma2(mcA[3], U3d, mul2(mcA[2], U2d));
        u64 cB1 = fma2(mcB[3], U3d, mul2(mcB[2], U2d));
        hA = add2(accA, add2(cA0, cA1));
        hB = add2(accB, add2(cB0, cB1));

        // ---- low-rank coordinate output (warp0 lane0) ----
        if (wid == 0 && lane == 0) {
            S01 = fma2(c9, S01, pack2(uf0, uf1));
            S23 = fma2(c9, S23, pack2(uf2, uf3));
            float o0, o1, o2, o3;
            unpack2(mul2(asq, S01), o0, o1);
            unpack2(mul2(asq, S23), o2, o3);
            *(float4*)(outb + (size_t)t * 20) = make_float4(o0, o1, o2, o3);
        }
    };

    for (int t = 0; t < TLEN; t += 2) {
        step(t,     0, pv0);
        step(t + 1, 1, pv1);
    }
}

extern "C" void kernel_launch(void* const* d_in, const int* in_sizes, int n_in,
                              void* d_out, int out_size) {
    const float* x = (const float*)d_in[0];
    const float* m = (const float*)d_in[1];
    const float* n = (const float*)d_in[2];
    const float* I = (const float*)d_in[3];
    cudaFuncSetAttribute(rnn_fused, cudaFuncAttributeMaxDynamicSharedMemorySize,
                         SMEM_TOTAL);
    rnn_fused<<<BATCH, NTHR, SMEM_TOTAL>>>(x, m, n, I, (float*)d_out);
}

// round 17
// speedup vs baseline: 1.1404x; 1.1404x over previous
#include <cuda_runtime.h>
#include <cstdint>

// MixtureLowRankRNN — GB300 sm_103a. Single fused kernel.
// Subspace identity: h_t ∈ colspan([m|I]) (h0=0) ⇒ outputs are basis coords:
//   y[:,t,0:4]  = a_s*S_{t+1},  S <- 0.9 S + u_t,  u_t = n^T tanh(h_t)
//   y[:,t,4:20] = 0.1*X_{t+1},  X <- 0.9 X + x_t
// Round 12: (a) redundant-redux cross-warp combine — each thread reads ONE
// int4 partial (lane&7) and redux-es: result is exactly 4U (int), the 1/4
// folds into scale constants; replaces 8 LDS.128 + 12 IADD. (b) the x-scan
// output moved to a parallel prologue (linear scan, 128-step warmup exact to
// fp32 noise) — no warp roles left inside the serial loop except warp0 lane0.

#define RANKN 4
#define INPN  16
#define TLEN  1024
#define BATCH 32
#define NTHR  256

#define S_Q   2097152.0f     // 2^21 fixed-point scale

typedef unsigned long long u64;

#define SMEM_X_BYTES  (TLEN * INPN * 8)          // duplicated pairs: 128 KB
#define SMEM_TOTAL    SMEM_X_BYTES

__device__ __forceinline__ u64 pack2(float x, float y) {
    u64 r; asm("mov.b64 %0, {%1, %2};" : "=l"(r) : "f"(x), "f"(y)); return r;
}
__device__ __forceinline__ void unpack2(u64 v, float& x, float& y) {
    asm("mov.b64 {%0, %1}, %2;" : "=f"(x), "=f"(y) : "l"(v));
}
__device__ __forceinline__ u64 fma2(u64 a, u64 b, u64 c) {
    u64 d; asm("fma.rn.f32x2 %0, %1, %2, %3;" : "=l"(d) : "l"(a), "l"(b), "l"(c)); return d;
}
__device__ __forceinline__ u64 mul2(u64 a, u64 b) {
    u64 d; asm("mul.rn.f32x2 %0, %1, %2;" : "=l"(d) : "l"(a), "l"(b)); return d;
}
__device__ __forceinline__ u64 add2(u64 a, u64 b) {
    u64 d; asm("add.rn.f32x2 %0, %1, %2;" : "=l"(d) : "l"(a), "l"(b)); return d;
}
__device__ __forceinline__ float tanha(float x) {
    float r; asm("tanh.approx.f32 %0, %1;" : "=f"(r) : "f"(x)); return r;
}
__device__ __forceinline__ int redux_s32(int v) {
    int r; asm("redux.sync.add.s32 %0, %1, 0xffffffff;" : "=r"(r) : "r"(v)); return r;
}

__global__ __launch_bounds__(NTHR, 1)
void rnn_fused(const float* __restrict__ x,   // [B, T, 16]
               const float* __restrict__ m,   // [H, 4]
               const float* __restrict__ n,   // [H, 4]
               const float* __restrict__ I,   // [H, 16]
               float* __restrict__ out)       // [B, T, 20]
{
    extern __shared__ char smem[];
    u64* s_xd = (u64*)smem;                    // [TLEN*16] duplicated x pairs

    __shared__ int4 s_ipart[2][8];             // [buf][warp] int partials

    const int b    = blockIdx.x;
    const int tid  = threadIdx.x;
    const int wid  = tid >> 5;
    const int lane = tid & 31;

    const float a_s  = 0.1f * (500.0f / 1024.0f);
    const float invS = 1.0f / S_Q;
    const float qsc  = 0.25f * a_s * invS;     // folds the 4x redux redundancy

    // ---- stage the whole batch's x into smem, duplicated as f32x2 pairs ----
    const float* xb = x + (size_t)b * TLEN * INPN;
    {
        const float4* xr4 = (const float4*)xb;
        for (int idx = tid; idx < TLEN * INPN / 4; idx += NTHR) {
            float4 f = xr4[idx];
            s_xd[idx * 4 + 0] = pack2(f.x, f.x);
            s_xd[idx * 4 + 1] = pack2(f.y, f.y);
            s_xd[idx * 4 + 2] = pack2(f.z, f.z);
            s_xd[idx * 4 + 3] = pack2(f.w, f.w);
        }
    }

    // ---- weights in registers (pairs: A=(tid,tid+256), B=(tid+512,tid+768)) ----
    const int eA0 = tid,       eA1 = tid + 256;
    const int eB0 = tid + 512, eB1 = tid + 768;

    u64 naA[RANKN], naB[RANKN], mcA[RANKN], mcB[RANKN], Ia[INPN], Ib[INPN];
#pragma unroll
    for (int r = 0; r < RANKN; r++) {
        naA[r] = pack2(S_Q * n[eA0 * RANKN + r], S_Q * n[eA1 * RANKN + r]);
        naB[r] = pack2(S_Q * n[eB0 * RANKN + r], S_Q * n[eB1 * RANKN + r]);
        mcA[r] = pack2(qsc * m[eA0 * RANKN + r], qsc * m[eA1 * RANKN + r]);
        mcB[r] = pack2(qsc * m[eB0 * RANKN + r], qsc * m[eB1 * RANKN + r]);
    }
#pragma unroll
    for (int j = 0; j < INPN; j++) {
        Ia[j] = pack2(0.1f * I[eA0 * INPN + j], 0.1f * I[eA1 * INPN + j]);
        Ib[j] = pack2(0.1f * I[eB0 * INPN + j], 0.1f * I[eB1 * INPN + j]);
    }

    const u64 c9  = pack2(0.9f, 0.9f);
    const u64 asq = pack2(qsc, qsc);           // output scale (4x folded)

    float* outb = out + (size_t)b * TLEN * 20;

    __syncthreads();   // x staging complete

    // ---- prologue: y[:,:,4:20] = 0.1 * decayed x scan, 16 parallel chunks ----
    // chunk c covers t in [c*64, c*64+64); warmup from max(0, t0-128) makes the
    // linear scan exact to fp32 noise (0.9^128 ~ 1.4e-6).
    {
        const int c  = tid >> 4;          // 0..15
        const int jj = tid & 15;          // 0..15
        const int t0 = c * (TLEN / 16);
        const int w0 = (t0 >= 128) ? (t0 - 128) : 0;
        float X = 0.f;
        for (int t = w0; t < t0; t++) {
            float lo, hi; unpack2(s_xd[(size_t)t * INPN + jj], lo, hi);
            X = fmaf(0.9f, X, lo); (void)hi;
        }
        float* ob = outb + 4 + jj;
#pragma unroll 4
        for (int t = t0; t < t0 + TLEN / 16; t++) {
            float lo, hi; unpack2(s_xd[(size_t)t * INPN + jj], lo, hi);
            X = fmaf(0.9f, X, lo); (void)hi;
            ob[(size_t)t * 20] = 0.1f * X;
        }
    }

    u64 hA = 0ull, hB = 0ull;
    u64 S01 = 0ull, S23 = 0ull;      // warp0 lane0, scaled domain (4*S_Q*u)

    for (int t = 0; t < TLEN; t++) {
        // ---- critical path: tanh(h), scaled low-rank dot, int redux ----
        float a0, a1, b0v, b1v;
        unpack2(hA, a0, a1); unpack2(hB, b0v, b1v);
        u64 thA = pack2(tanha(a0), tanha(a1));
        u64 thB = pack2(tanha(b0v), tanha(b1v));

        int pi[4];
#pragma unroll
        for (int r = 0; r < RANKN; r++) {
            float lo, hi; unpack2(fma2(naB[r], thB, mul2(naA[r], thA)), lo, hi);
            pi[r] = redux_s32(__float2int_rn(lo + hi));
        }
        if (lane == 0) s_ipart[t & 1][wid] = make_int4(pi[0], pi[1], pi[2], pi[3]);

        // ---- u-independent update from smem x: 8 LDS.128 + 4 parallel chains ----
        const ulonglong2* xp = (const ulonglong2*)(s_xd + (size_t)t * INPN);
        ulonglong2 xq0 = xp[0], xq1 = xp[1], xq2 = xp[2], xq3 = xp[3];
        u64 aA0 = fma2(c9, hA, mul2(Ia[0], xq0.x));
        u64 aB0 = fma2(c9, hB, mul2(Ib[0], xq0.x));
        u64 aA1 = fma2(Ia[2], xq1.x, mul2(Ia[1], xq0.y));
        u64 aB1 = fma2(Ib[2], xq1.x, mul2(Ib[1], xq0.y));
        u64 aA2 = fma2(Ia[4], xq2.x, mul2(Ia[3], xq1.y));
        u64 aB2 = fma2(Ib[4], xq2.x, mul2(Ib[3], xq1.y));
        u64 aA3 = fma2(Ia[6], xq3.x, mul2(Ia[5], xq2.y));
        u64 aB3 = fma2(Ib[6], xq3.x, mul2(Ib[5], xq2.y));
        ulonglong2 xq4 = xp[4], xq5 = xp[5], xq6 = xp[6], xq7 = xp[7];
        aA0 = fma2(Ia[7],  xq3.y, aA0);  aB0 = fma2(Ib[7],  xq3.y, aB0);
        aA1 = fma2(Ia[8],  xq4.x, aA1);  aB1 = fma2(Ib[8],  xq4.x, aB1);
        aA2 = fma2(Ia[9],  xq4.y, aA2);  aB2 = fma2(Ib[9],  xq4.y, aB2);
        aA3 = fma2(Ia[10], xq5.x, aA3);  aB3 = fma2(Ib[10], xq5.x, aB3);
        aA0 = fma2(Ia[11], xq5.y, aA0);  aB0 = fma2(Ib[11], xq5.y, aB0);
        aA1 = fma2(Ia[12], xq6.x, aA1);  aB1 = fma2(Ib[12], xq6.x, aB1);
        aA2 = fma2(Ia[13], xq6.y, aA2);  aB2 = fma2(Ib[13], xq6.y, aB2);
        aA3 = fma2(Ia[14], xq7.x, aA3);  aB3 = fma2(Ib[14], xq7.x, aB3);
        aA0 = fma2(Ia[15], xq7.y, aA0);  aB0 = fma2(Ib[15], xq7.y, aB0);
        u64 accA = add2(add2(aA0, aA1), add2(aA2, aA3));
        u64 accB = add2(add2(aB0, aB1), add2(aB2, aB3));

        __syncthreads();   // the only barrier per step

        // ---- combine: ONE LDS.128 + 4 redux (each partial counted 4x) ----
        int4 v = s_ipart[t & 1][lane & 7];
        int U0 = redux_s32(v.x);    // exactly 4*U_r (integers)
        int U1 = redux_s32(v.y);
        int U2 = redux_s32(v.z);
        int U3 = redux_s32(v.w);

        float uf0 = (float)U0, uf1 = (float)U1;   // 4*S_Q*u_r
        float uf2 = (float)U2, uf3 = (float)U3;
        u64 U0d = pack2(uf0, uf0), U1d = pack2(uf1, uf1);
        u64 U2d = pack2(uf2, uf2), U3d = pack2(uf3, uf3);

        // h_{t+1} = acc + sum_r (qsc*m_r) * (4*S_Q*u_r)
        u64 cA0 = fma2(mcA[1], U1d, mul2(mcA[0], U0d));
        u64 cB0 = fma2(mcB[1], U1d, mul2(mcB[0], U0d));
        u64 cA1 = fma2(mcA[3], U3d, mul2(mcA[2], U2d));
        u64 cB1 = fma2(mcB[3], U3d, mul2(mcB[2], U2d));
        hA = add2(accA, add2(cA0, cA1));
        hB = add2(accB, add2(cB0, cB1));

        // ---- low-rank coordinate output (warp0 lane0) ----
        if (wid == 0 && lane == 0) {
            S01 = fma2(c9, S01, pack2(uf0, uf1));
            S23 = fma2(c9, S23, pack2(uf2, uf3));
            float o0, o1, o2, o3;
            unpack2(mul2(asq, S01), o0, o1);
            unpack2(mul2(asq, S23), o2, o3);
            *(float4*)(outb + (size_t)t * 20) = make_float4(o0, o1, o2, o3);
        }
    }
}

extern "C" void kernel_launch(void* const* d_in, const int* in_sizes, int n_in,
                              void* d_out, int out_size) {
    const float* x = (const float*)d_in[0];
    const float* m = (const float*)d_in[1];
    const float* n = (const float*)d_in[2];
    const float* I = (const float*)d_in[3];
    cudaFuncSetAttribute(rnn_fused, cudaFuncAttributeMaxDynamicSharedMemorySize,
                         SMEM_TOTAL);
    rnn_fused<<<BATCH, NTHR, SMEM_TOTAL>>>(x, m, n, I, (float*)d_out);
}